// round 11
// baseline (speedup 1.0000x reference)
#include <cuda_runtime.h>
#include <cuda_fp16.h>
#include <cstdint>

#define ED   128
#define AD   64
#define THREADS 256
#define ROWB 272u        // padded row stride (136 fp16); frag loads conflict-free (4r+t pattern)

// ---- shared memory layout (bytes) ----
#define A_OFF     0u         // 200 rows x 272 B = 54400
#define W_OFF     54400u     // 64 rows x 272 B = 17408 -> 71808 ; reused as float4 PART after GEMM
#define W2_OFF    71808u     // 64 f32 -> 72064
#define WARR_OFF  72064u     // 208 f32 -> 72896
#define CPART_OFF 72896u     // 128 f32 -> 73408
#define B2_OFF    73408u
#define SMEM_BYTES 73424u    // x3 CTAs = 220.3 KB <= 228 KB

static __device__ __forceinline__ void mma16816(
    float c[4], const uint32_t a[4], uint32_t b0, uint32_t b1)
{
    asm volatile(
        "mma.sync.aligned.m16n8k16.row.col.f32.f16.f16.f32 "
        "{%0,%1,%2,%3}, {%4,%5,%6,%7}, {%8,%9}, {%0,%1,%2,%3};"
        : "+f"(c[0]), "+f"(c[1]), "+f"(c[2]), "+f"(c[3])
        : "r"(a[0]), "r"(a[1]), "r"(a[2]), "r"(a[3]), "r"(b0), "r"(b1));
}

__global__ void __launch_bounds__(THREADS, 3)
attn_din_kernel(const float* __restrict__ behav,
                const float* __restrict__ target,
                const float* __restrict__ W1,
                const float* __restrict__ b1,
                const float* __restrict__ W2,
                const float* __restrict__ b2,
                float* __restrict__ out)
{
    extern __shared__ char smem[];
    const int tid  = threadIdx.x;
    const int wid  = tid >> 5;
    const int lane = tid & 31;
    const int b    = blockIdx.x;

    float* w2S = (float*)(smem + W2_OFF);
    float* wAr = (float*)(smem + WARR_OFF);
    float* cP  = (float*)(smem + CPART_OFF);

    if (tid < AD) w2S[tid] = W2[tid];
    if (tid == 64) *((float*)(smem + B2_OFF)) = b2[0];

    // ================= phase 0 (warp-specialized, fully parallel) =================
    if (wid < 4) {
        // warps 0-3: stage ALL 200 A rows (fp16), warp w -> rows w, w+4, ... (50-deep stream)
        const float4* bp = (const float4*)(behav + (size_t)b * 200 * ED);
#pragma unroll 5
        for (int i = 0; i < 50; i++) {
            int r = wid + i * 4;
            float4 v = bp[r * 32 + lane];
            __half2 h01 = __floats2half2_rn(v.x, v.y);
            __half2 h23 = __floats2half2_rn(v.z, v.w);
            uint32_t off = (uint32_t)r * ROWB + (uint32_t)lane * 8u;
            *reinterpret_cast<uint2*>(smem + A_OFF + off) =
                make_uint2(*(uint32_t*)&h01, *(uint32_t*)&h23);
        }
    } else {
        // warps 4-7: build W_b[a][k] = Wx + Wd + t[k]*Wm (fp16) and c-partials.
        const int j  = tid - 128;
        const int a  = j & 63;
        const int kh = j >> 6;
        const float* tg  = target + (size_t)b * ED + kh * 64;
        const float* w1p = W1 + (size_t)(kh * 64) * AD + a;
        float cacc = (kh == 0) ? b1[a] : 0.f;
#pragma unroll 4
        for (int kk = 0; kk < 64; kk++) {
            float tk = tg[kk];                              // warp-broadcast, L2-hot
            float wx = w1p[kk * AD];                        // coalesced
            float wt = w1p[(128 * AD) + kk * AD];
            float wm = w1p[(256 * AD) + kk * AD];
            float wd = w1p[(384 * AD) + kk * AD];
            float w  = wx + wd + tk * wm;
            int k = kh * 64 + kk;
            *reinterpret_cast<__half*>(smem + W_OFF + (uint32_t)a * ROWB + (uint32_t)k * 2u)
                = __float2half_rn(w);
            cacc = fmaf(tk, wt - wd, cacc);
        }
        cP[j] = cacc;                                       // c[a] = cP[a] + cP[64+a]
    }
    __syncthreads();   // A(200), W, cP, w2S, b2 all ready

    const int g  = lane >> 2;
    const int t2 = (lane & 3) * 2;
    const float b2v = *((const float*)(smem + B2_OFF));

    // ---- GEMM + epilogue: warp w handles m16 tiles {w, w+8} (tiles 0..12) ----
    for (int tile = wid; tile < 13; tile += 8) {
        float acc[8][4];
#pragma unroll
        for (int n = 0; n < 8; n++)
#pragma unroll
            for (int i = 0; i < 4; i++) acc[n][i] = 0.f;

        // tile 12 rows 200-207 read into the W region -> finite fp16 garbage,
        // row-isolated in MMA, masked by the s<200 guard below.
#pragma unroll
        for (int ks = 0; ks < 8; ks++) {
            const uint32_t kb = (uint32_t)(ks * 16 + t2) * 2u;
            const char* base = smem + A_OFF + (uint32_t)(tile * 16 + g) * ROWB + kb;
            uint32_t a[4];
            a[0] = *(const uint32_t*)(base);
            a[1] = *(const uint32_t*)(base + 8 * ROWB);
            a[2] = *(const uint32_t*)(base + 16);
            a[3] = *(const uint32_t*)(base + 8 * ROWB + 16);
#pragma unroll
            for (int n = 0; n < 8; n++) {
                const char* wb = smem + W_OFF + (uint32_t)(n * 8 + g) * ROWB + kb;
                uint32_t b0  = *(const uint32_t*)(wb);
                uint32_t b1r = *(const uint32_t*)(wb + 16);
                mma16816(acc[n], a, b0, b1r);
            }
        }

        // epilogue: z = b2 + sum_a relu(D + c)*W2 ; wAr = sigmoid(z) (0 if s>=200)
#pragma unroll
        for (int h = 0; h < 2; h++) {
            float z = 0.f;
#pragma unroll
            for (int n = 0; n < 8; n++) {
                int col = n * 8 + t2;
                float c0 = cP[col]     + cP[64 + col];
                float c1 = cP[col + 1] + cP[65 + col];
                float h0 = fmaxf(acc[n][2 * h]     + c0, 0.f);
                float h1 = fmaxf(acc[n][2 * h + 1] + c1, 0.f);
                z = fmaf(h0, w2S[col], z);
                z = fmaf(h1, w2S[col + 1], z);
            }
            z += __shfl_xor_sync(0xFFFFFFFFu, z, 1);
            z += __shfl_xor_sync(0xFFFFFFFFu, z, 2);
            int s = tile * 16 + h * 8 + g;
            if ((lane & 3) == 0 && s < 208) {
                float wgt = (s < 200) ? (1.f / (1.f + __expf(-(z + b2v)))) : 0.f;
                wAr[s] = wgt;
            }
        }
    }
    __syncthreads();   // all wAr[0..199] ready; W region now dead

    // ---- weighted sum: thread (q=tid>>5, lane) -> 4 e-values x 25 rows ----
    {
        const int q = tid >> 5;
        float4 acc4 = make_float4(0.f, 0.f, 0.f, 0.f);
        const char* base = smem + A_OFF + (uint32_t)lane * 8u;
#pragma unroll 5
        for (int i = 0; i < 25; i++) {
            int s = q * 25 + i;
            uint2 d = *reinterpret_cast<const uint2*>(base + (uint32_t)s * ROWB);
            float2 f01 = __half22float2(*reinterpret_cast<__half2*>(&d.x));
            float2 f23 = __half22float2(*reinterpret_cast<__half2*>(&d.y));
            float ws = wAr[s];
            acc4.x = fmaf(ws, f01.x, acc4.x);
            acc4.y = fmaf(ws, f01.y, acc4.y);
            acc4.z = fmaf(ws, f23.x, acc4.z);
            acc4.w = fmaf(ws, f23.y, acc4.w);
        }
        __syncthreads();   // ensure GEMM readers of W are long done (already true) / order reuse
        ((float4*)(smem + W_OFF))[q * 32 + lane] = acc4;
    }
    __syncthreads();

    if (tid < 32) {
        const float4* p = (const float4*)(smem + W_OFF);
        float4 s0 = p[tid];
#pragma unroll
        for (int k = 1; k < 8; k++) {
            float4 v = p[k * 32 + tid];
            s0.x += v.x; s0.y += v.y; s0.z += v.z; s0.w += v.w;
        }
        *reinterpret_cast<float4*>(out + (size_t)b * ED + tid * 4) = s0;
    }
}

extern "C" void kernel_launch(void* const* d_in, const int* in_sizes, int n_in,
                              void* d_out, int out_size)
{
    const float* behav  = (const float*)d_in[0];
    const float* target = (const float*)d_in[1];
    const float* W1     = (const float*)d_in[2];
    const float* b1     = (const float*)d_in[3];
    const float* W2     = (const float*)d_in[4];
    const float* b2     = (const float*)d_in[5];
    float* out = (float*)d_out;

    const int B = in_sizes[1] / ED;   // 2048

    static bool attr_set = false;
    if (!attr_set) {
        cudaFuncSetAttribute(attn_din_kernel,
                             cudaFuncAttributeMaxDynamicSharedMemorySize, (int)SMEM_BYTES);
        attr_set = true;
    }

    attn_din_kernel<<<B, THREADS, SMEM_BYTES>>>(behav, target, W1, b1, W2, b2, out);
}